// round 8
// baseline (speedup 1.0000x reference)
#include <cuda_runtime.h>
#include <cstdint>

// ---------------- problem constants ----------------
#define NROWS   16384
#define DDIM    256
#define KCODES  8192
#define DECAY   0.99f
#define ONE_M_DECAY 0.01f
#define EPSV    1e-5f

// output layout (concatenated, float32, tuple order)
#define OFF_Q     0L
#define OFF_LOSS  4194304L
#define OFF_IDX   4194305L
#define OFF_CS    4210689L
#define OFF_EMAW  4218881L
#define OFF_EMB   6316033L

// ---------------- scratch ----------------
__device__ float g_emb [KCODES * DDIM];
__device__ float g_ehi [KCODES * DDIM];
__device__ float g_elo [KCODES * DDIM];
__device__ float g_xhi [NROWS * DDIM];
__device__ float g_xlo [NROWS * DDIM];
__device__ float g_embsq[KCODES];
__device__ int   g_idx [NROWS];
__device__ float g_counts[KCODES];
__device__ float g_dw  [KCODES * DDIM];
__device__ float g_loss;
__device__ float g_nsum;

// ---------------- helpers ----------------
__device__ __forceinline__ float tf32_rnd(float v) {
    uint32_t u;
    asm("cvt.rna.tf32.f32 %0, %1;" : "=r"(u) : "f"(v));
    return __uint_as_float(u);
}
__device__ __forceinline__ void cpa16(uint32_t dst, const float* src) {
    asm volatile("cp.async.cg.shared.global [%0], [%1], 16;" :: "r"(dst), "l"(src));
}
__device__ __forceinline__ void cpa_commit() { asm volatile("cp.async.commit_group;"); }
__device__ __forceinline__ void cpa_wait1()  { asm volatile("cp.async.wait_group 1;" ::: "memory"); }
__device__ __forceinline__ void cpa_wait0()  { asm volatile("cp.async.wait_group 0;" ::: "memory"); }
__device__ __forceinline__ uint32_t smem_u32(const void* p) {
    uint32_t a;
    asm("{ .reg .u64 t; cvta.to.shared.u64 t, %1; cvt.u32.u64 %0, t; }" : "=r"(a) : "l"(p));
    return a;
}
__device__ __forceinline__ void mma16n8k8(float c[4],
                                          uint32_t a0, uint32_t a1, uint32_t a2, uint32_t a3,
                                          uint32_t b0, uint32_t b1) {
    asm volatile(
        "mma.sync.aligned.m16n8k8.row.col.f32.tf32.tf32.f32 "
        "{%0,%1,%2,%3}, {%4,%5,%6,%7}, {%8,%9}, {%0,%1,%2,%3};"
        : "+f"(c[0]), "+f"(c[1]), "+f"(c[2]), "+f"(c[3])
        : "r"(a0), "r"(a1), "r"(a2), "r"(a3), "r"(b0), "r"(b1));
}

// ---------------- kernel 0: zero scratch ----------------
__global__ void zero_kernel() {
    long total = (long)KCODES * DDIM + KCODES + 2;
    for (long i = (long)blockIdx.x * blockDim.x + threadIdx.x; i < total;
         i += (long)gridDim.x * blockDim.x) {
        if (i < (long)KCODES * DDIM)               g_dw[i] = 0.f;
        else if (i < (long)KCODES * DDIM + KCODES) g_counts[i - (long)KCODES * DDIM] = 0.f;
        else if (i == (long)KCODES * DDIM + KCODES) g_loss = 0.f;
        else                                        g_nsum = 0.f;
    }
}

// ---------------- kernel 1a: split x into tf32 hi/lo ----------------
__global__ void xsplit_kernel(const float* __restrict__ x) {
    long i = (long)blockIdx.x * 256 + threadIdx.x;
    float v = x[i];
    float h = tf32_rnd(v);
    g_xhi[i] = h;
    g_xlo[i] = tf32_rnd(v - h);
}

// ---------------- kernel 1b: affine codebook + split + norms ----------------
__global__ void prep_kernel(const float* __restrict__ embedding,
                            const float* __restrict__ amean,
                            const float* __restrict__ astd) {
    int k = blockIdx.x;
    int d = threadIdx.x;
    long i = (long)k * DDIM + d;
    float v = amean[d] + astd[d] * embedding[i];
    g_emb[i] = v;
    float h = tf32_rnd(v);
    g_ehi[i] = h;
    g_elo[i] = tf32_rnd(v - h);

    float s = v * v;
    #pragma unroll
    for (int off = 16; off; off >>= 1) s += __shfl_down_sync(0xffffffffu, s, off);
    __shared__ float ws[8];
    if ((d & 31) == 0) ws[d >> 5] = s;
    __syncthreads();
    if (d == 0) {
        float t = 0.f;
        #pragma unroll
        for (int i2 = 0; i2 < 8; i2++) t += ws[i2];
        g_embsq[k] = t;
    }
}

// ---------------- kernel 2: mma.sync tf32 distance GEMM + argmin ----------------
// 128 CTAs x 256 threads (8 warps). CTA: M=128 rows; 64 chunks of N=128 codes;
// K in 8 slabs of 32, cp.async double-buffered. Warp tile 64x32 (grid 2m x 4n).
// acc = 4x4x4 = 64 regs/thread -> no spills (R7 had 128 -> regs=255, spilling).
#define NCHUNK   128
#define NSLABS   8
#define NCHUNKS  (KCODES / NCHUNK)    // 64
#define GTOT     (NCHUNKS * NSLABS)   // 512
#define RS       36                   // smem row stride in floats (conflict-free)
#define A_F      (128 * RS)           // 4608 floats per A split
#define B_F      (NCHUNK * RS)        // 4608 floats per B split
#define BUF_F    (2 * A_F + 2 * B_F)  // 18432 floats = 73728 B per buffer
#define FOFF_AHI 0
#define FOFF_ALO A_F
#define FOFF_BHI (2 * A_F)
#define FOFF_BLO (2 * A_F + B_F)

__global__ void __launch_bounds__(256, 1)
argmin_kernel() {
    extern __shared__ float dsm[];
    __shared__ float s_minv[128][4];
    __shared__ int   s_mini[128][4];

    const int tid   = threadIdx.x;
    const int wid   = tid >> 5;
    const int lane  = tid & 31;
    const int qrow  = lane >> 2;     // 0..7
    const int qcol  = lane & 3;      // 0..3
    const int warpM = wid & 1;       // 2 row-groups of warps (64 rows each)
    const int warpN = wid >> 1;      // 4 col-groups (32 cols each)
    const int rowBase = blockIdx.x * 128;

    const uint32_t dynb = smem_u32(dsm);

    // stage slab g into buffer g&1
    auto stage = [&](int g) {
        const uint32_t base = dynb + (uint32_t)(g & 1) * (BUF_F * 4);
        const int ks = g & 7, ch = g >> 3;
        const float* xh = g_xhi + (long)rowBase * DDIM + ks * 32;
        const float* xl = g_xlo + (long)rowBase * DDIM + ks * 32;
        const float* eh = g_ehi + (long)ch * NCHUNK * DDIM + ks * 32;
        const float* el = g_elo + (long)ch * NCHUNK * DDIM + ks * 32;
        #pragma unroll
        for (int i = tid; i < 1024; i += 256) {       // A: 128 rows x 8 seg
            int r = i >> 3, sg = i & 7;
            uint32_t o = (uint32_t)(r * RS + sg * 4) * 4;
            cpa16(base + FOFF_AHI * 4 + o, xh + (long)r * DDIM + sg * 4);
            cpa16(base + FOFF_ALO * 4 + o, xl + (long)r * DDIM + sg * 4);
        }
        #pragma unroll
        for (int i = tid; i < 1024; i += 256) {       // B: 128 rows x 8 seg
            int r = i >> 3, sg = i & 7;
            uint32_t o = (uint32_t)(r * RS + sg * 4) * 4;
            cpa16(base + FOFF_BHI * 4 + o, eh + (long)r * DDIM + sg * 4);
            cpa16(base + FOFF_BLO * 4 + o, el + (long)r * DDIM + sg * 4);
        }
    };

    stage(0);
    cpa_commit();

    float acc[4][4][4];     // [mt][nt][frag] -> 64 regs
    #pragma unroll
    for (int mt = 0; mt < 4; mt++)
        #pragma unroll
        for (int nt = 0; nt < 4; nt++)
            #pragma unroll
            for (int f = 0; f < 4; f++) acc[mt][nt][f] = 0.f;

    float minv[8];
    int   mini[8];
    #pragma unroll
    for (int s = 0; s < 8; s++) { minv[s] = 3.4e38f; mini[s] = 0; }

    for (int g = 0; g < GTOT; g++) {
        if (g + 1 < GTOT) { stage(g + 1); cpa_commit(); cpa_wait1(); }
        else              { cpa_wait0(); }
        __syncthreads();

        const float* buf = dsm + (g & 1) * BUF_F;
        const uint32_t* Ah = (const uint32_t*)(buf + FOFF_AHI);
        const uint32_t* Al = (const uint32_t*)(buf + FOFF_ALO);
        const uint32_t* Bh = (const uint32_t*)(buf + FOFF_BHI);
        const uint32_t* Bl = (const uint32_t*)(buf + FOFF_BLO);

        #pragma unroll
        for (int k8 = 0; k8 < 4; k8++) {
            const int kk = k8 * 8;
            uint32_t ah[4][4], al[4][4], bh[4][2];
            #pragma unroll
            for (int mt = 0; mt < 4; mt++) {
                int ra = (warpM * 64 + mt * 16 + qrow) * RS + kk + qcol;
                ah[mt][0] = Ah[ra];            ah[mt][1] = Ah[ra + 8 * RS];
                ah[mt][2] = Ah[ra + 4];        ah[mt][3] = Ah[ra + 8 * RS + 4];
                al[mt][0] = Al[ra];            al[mt][1] = Al[ra + 8 * RS];
                al[mt][2] = Al[ra + 4];        al[mt][3] = Al[ra + 8 * RS + 4];
            }
            #pragma unroll
            for (int nt = 0; nt < 4; nt++) {
                int rb = (warpN * 32 + nt * 8 + qrow) * RS + kk + qcol;
                bh[nt][0] = Bh[rb];
                bh[nt][1] = Bh[rb + 4];
            }
            // split 0: hi x hi
            #pragma unroll
            for (int nt = 0; nt < 4; nt++)
                #pragma unroll
                for (int mt = 0; mt < 4; mt++)
                    mma16n8k8(acc[mt][nt], ah[mt][0], ah[mt][1], ah[mt][2], ah[mt][3],
                              bh[nt][0], bh[nt][1]);
            // split 1: lo x hi
            #pragma unroll
            for (int nt = 0; nt < 4; nt++)
                #pragma unroll
                for (int mt = 0; mt < 4; mt++)
                    mma16n8k8(acc[mt][nt], al[mt][0], al[mt][1], al[mt][2], al[mt][3],
                              bh[nt][0], bh[nt][1]);
            // split 2: hi x lo
            #pragma unroll
            for (int nt = 0; nt < 4; nt++) {
                int rb = (warpN * 32 + nt * 8 + qrow) * RS + kk + qcol;
                uint32_t bl0 = Bl[rb], bl1 = Bl[rb + 4];
                #pragma unroll
                for (int mt = 0; mt < 4; mt++)
                    mma16n8k8(acc[mt][nt], ah[mt][0], ah[mt][1], ah[mt][2], ah[mt][3],
                              bl0, bl1);
            }
        }

        if ((g & 7) == 7) {       // chunk complete: fold into running argmin
            const int chunk = g >> 3;
            #pragma unroll
            for (int nt = 0; nt < 4; nt++) {
                int col0 = chunk * NCHUNK + warpN * 32 + nt * 8 + 2 * qcol;
                float e0 = g_embsq[col0];
                float e1 = g_embsq[col0 + 1];
                #pragma unroll
                for (int mt = 0; mt < 4; mt++) {
                    float d0 = fmaf(-2.f, acc[mt][nt][0], e0);
                    float d1 = fmaf(-2.f, acc[mt][nt][1], e1);
                    float d2 = fmaf(-2.f, acc[mt][nt][2], e0);
                    float d3 = fmaf(-2.f, acc[mt][nt][3], e1);
                    int s0 = mt * 2, s1 = mt * 2 + 1;
                    if (d0 < minv[s0]) { minv[s0] = d0; mini[s0] = col0; }
                    if (d1 < minv[s0]) { minv[s0] = d1; mini[s0] = col0 + 1; }
                    if (d2 < minv[s1]) { minv[s1] = d2; mini[s1] = col0; }
                    if (d3 < minv[s1]) { minv[s1] = d3; mini[s1] = col0 + 1; }
                    acc[mt][nt][0] = 0.f; acc[mt][nt][1] = 0.f;
                    acc[mt][nt][2] = 0.f; acc[mt][nt][3] = 0.f;
                }
            }
        }
        __syncthreads();
    }

    // reduce: quad (lanes sharing a row) then across warpN via smem
    #pragma unroll
    for (int mt = 0; mt < 4; mt++)
        #pragma unroll
        for (int h = 0; h < 2; h++) {
            int s = mt * 2 + h;
            float v = minv[s];
            int   idx = mini[s];
            #pragma unroll
            for (int off = 1; off <= 2; off <<= 1) {
                float ov = __shfl_xor_sync(0xffffffffu, v, off);
                int   oi = __shfl_xor_sync(0xffffffffu, idx, off);
                if (ov < v || (ov == v && oi < idx)) { v = ov; idx = oi; }
            }
            if (qcol == 0) {
                int row = warpM * 64 + mt * 16 + h * 8 + qrow;
                s_minv[row][warpN] = v;
                s_mini[row][warpN] = idx;
            }
        }
    __syncthreads();
    if (tid < 128) {
        float bv = s_minv[tid][0];
        int   bi = s_mini[tid][0];
        #pragma unroll
        for (int n = 1; n < 4; n++) {
            float v = s_minv[tid][n];
            int   i = s_mini[tid][n];
            if (v < bv || (v == bv && i < bi)) { bv = v; bi = i; }
        }
        g_idx[rowBase + tid] = bi;
    }
}

// ---------------- kernel 3: gather quantized, loss, scatter EMA stats ----------------
__global__ void gather_kernel(const float* __restrict__ x, float* __restrict__ out) {
    int row = blockIdx.x;
    int d = threadIdx.x;
    int idx = g_idx[row];
    float xv = x[(long)row * DDIM + d];
    float qv = g_emb[(long)idx * DDIM + d];
    out[OFF_Q + (long)row * DDIM + d] = qv;

    float diff = qv - xv;
    float s = diff * diff;
    #pragma unroll
    for (int off = 16; off; off >>= 1) s += __shfl_down_sync(0xffffffffu, s, off);
    __shared__ float ws[8];
    if ((d & 31) == 0) ws[d >> 5] = s;
    __syncthreads();
    if (d == 0) {
        float t = 0.f;
        #pragma unroll
        for (int i = 0; i < 8; i++) t += ws[i];
        atomicAdd(&g_loss, t);
        atomicAdd(&g_counts[idx], 1.0f);
        out[OFF_IDX + row] = (float)idx;
    }
    atomicAdd(&g_dw[(long)idx * DDIM + d], xv);
}

// ---------------- kernel 4a: new_cluster_size + sum n ----------------
__global__ void cs_kernel(const float* __restrict__ cluster_size, float* __restrict__ out) {
    int k = blockIdx.x * 256 + threadIdx.x;
    float ncs = cluster_size[k] * DECAY + ONE_M_DECAY * g_counts[k];
    out[OFF_CS + k] = ncs;
    float s = ncs;
    #pragma unroll
    for (int off = 16; off; off >>= 1) s += __shfl_down_sync(0xffffffffu, s, off);
    __shared__ float ws[8];
    if ((threadIdx.x & 31) == 0) ws[threadIdx.x >> 5] = s;
    __syncthreads();
    if (threadIdx.x == 0) {
        float t = 0.f;
        #pragma unroll
        for (int i = 0; i < 8; i++) t += ws[i];
        atomicAdd(&g_nsum, t);
    }
}

// ---------------- kernel 4b: new_ema_w ----------------
__global__ void emaw_kernel(const float* __restrict__ ema_w, float* __restrict__ out) {
    long i = (long)blockIdx.x * blockDim.x + threadIdx.x;
    if (i < (long)KCODES * DDIM)
        out[OFF_EMAW + i] = ema_w[i] * DECAY + ONE_M_DECAY * g_dw[i];
}

// ---------------- kernel 5: smoothed normalize + loss write ----------------
__global__ void final_kernel(float* __restrict__ out) {
    int k = blockIdx.x;
    int d = threadIdx.x;
    float n = g_nsum;
    float ncs = out[OFF_CS + k];
    float smoothed = (ncs + EPSV) / (n + (float)KCODES * EPSV) * n;
    out[OFF_EMB + (long)k * DDIM + d] = out[OFF_EMAW + (long)k * DDIM + d] / smoothed;
    if (k == 0 && d == 0)
        out[OFF_LOSS] = 2.0f * g_loss / (float)((long)NROWS * DDIM);
}

// ---------------- launch ----------------
extern "C" void kernel_launch(void* const* d_in, const int* in_sizes, int n_in,
                              void* d_out, int out_size) {
    const float* x         = (const float*)d_in[0];
    const float* embedding = (const float*)d_in[1];
    const float* amean     = (const float*)d_in[2];
    const float* astd      = (const float*)d_in[3];
    const float* cs        = (const float*)d_in[4];
    const float* ema_w     = (const float*)d_in[5];
    float* out = (float*)d_out;

    (void)in_sizes; (void)n_in; (void)out_size;

    cudaFuncSetAttribute(argmin_kernel, cudaFuncAttributeMaxDynamicSharedMemorySize,
                         2 * BUF_F * 4);

    zero_kernel<<<2048, 256>>>();
    xsplit_kernel<<<NROWS * DDIM / 256, 256>>>(x);
    prep_kernel<<<KCODES, 256>>>(embedding, amean, astd);
    argmin_kernel<<<NROWS / 128, 256, 2 * BUF_F * 4>>>();
    gather_kernel<<<NROWS, 256>>>(x, out);
    cs_kernel<<<KCODES / 256, 256>>>(cs, out);
    emaw_kernel<<<(KCODES * DDIM + 255) / 256, 256>>>(ema_w, out);
    final_kernel<<<KCODES, 256>>>(out);
}

// round 9
// speedup vs baseline: 1.0565x; 1.0565x over previous
#include <cuda_runtime.h>
#include <cstdint>

// ---------------- problem constants ----------------
#define NROWS   16384
#define DDIM    256
#define KCODES  8192
#define DECAY   0.99f
#define ONE_M_DECAY 0.01f
#define EPSV    1e-5f

// output layout (concatenated, float32, tuple order)
#define OFF_Q     0L
#define OFF_LOSS  4194304L
#define OFF_IDX   4194305L
#define OFF_CS    4210689L
#define OFF_EMAW  4218881L
#define OFF_EMB   6316033L

// ---------------- scratch ----------------
__device__ float g_emb [KCODES * DDIM];
__device__ float g_ehi [KCODES * DDIM];
__device__ float g_elo [KCODES * DDIM];
__device__ float g_xhi [NROWS * DDIM];
__device__ float g_xlo [NROWS * DDIM];
__device__ float g_embsq[KCODES];
__device__ int   g_idx [NROWS];
__device__ float g_counts[KCODES];
__device__ float g_dw  [KCODES * DDIM];
__device__ float g_loss;
__device__ float g_nsum;

// ---------------- helpers ----------------
__device__ __forceinline__ float tf32_rnd(float v) {
    uint32_t u;
    asm("cvt.rna.tf32.f32 %0, %1;" : "=r"(u) : "f"(v));
    return __uint_as_float(u);
}
__device__ __forceinline__ void cpa16(uint32_t dst, const float* src) {
    asm volatile("cp.async.cg.shared.global [%0], [%1], 16;" :: "r"(dst), "l"(src));
}
__device__ __forceinline__ void cpa_commit() { asm volatile("cp.async.commit_group;"); }
__device__ __forceinline__ void cpa_wait1()  { asm volatile("cp.async.wait_group 1;" ::: "memory"); }
__device__ __forceinline__ void cpa_wait0()  { asm volatile("cp.async.wait_group 0;" ::: "memory"); }
__device__ __forceinline__ uint32_t smem_u32(const void* p) {
    uint32_t a;
    asm("{ .reg .u64 t; cvta.to.shared.u64 t, %1; cvt.u32.u64 %0, t; }" : "=r"(a) : "l"(p));
    return a;
}
__device__ __forceinline__ void mma16n8k8(float c[4],
                                          uint32_t a0, uint32_t a1, uint32_t a2, uint32_t a3,
                                          uint32_t b0, uint32_t b1) {
    asm volatile(
        "mma.sync.aligned.m16n8k8.row.col.f32.tf32.tf32.f32 "
        "{%0,%1,%2,%3}, {%4,%5,%6,%7}, {%8,%9}, {%0,%1,%2,%3};"
        : "+f"(c[0]), "+f"(c[1]), "+f"(c[2]), "+f"(c[3])
        : "r"(a0), "r"(a1), "r"(a2), "r"(a3), "r"(b0), "r"(b1));
}

// ---------------- kernel 0: zero scratch ----------------
__global__ void zero_kernel() {
    long total = (long)KCODES * DDIM + KCODES + 2;
    for (long i = (long)blockIdx.x * blockDim.x + threadIdx.x; i < total;
         i += (long)gridDim.x * blockDim.x) {
        if (i < (long)KCODES * DDIM)               g_dw[i] = 0.f;
        else if (i < (long)KCODES * DDIM + KCODES) g_counts[i - (long)KCODES * DDIM] = 0.f;
        else if (i == (long)KCODES * DDIM + KCODES) g_loss = 0.f;
        else                                        g_nsum = 0.f;
    }
}

// ---------------- kernel 1a: split x into tf32 hi/lo ----------------
__global__ void xsplit_kernel(const float* __restrict__ x) {
    long i = (long)blockIdx.x * 256 + threadIdx.x;
    float v = x[i];
    float h = tf32_rnd(v);
    g_xhi[i] = h;
    g_xlo[i] = tf32_rnd(v - h);
}

// ---------------- kernel 1b: affine codebook + split + norms ----------------
__global__ void prep_kernel(const float* __restrict__ embedding,
                            const float* __restrict__ amean,
                            const float* __restrict__ astd) {
    int k = blockIdx.x;
    int d = threadIdx.x;
    long i = (long)k * DDIM + d;
    float v = amean[d] + astd[d] * embedding[i];
    g_emb[i] = v;
    float h = tf32_rnd(v);
    g_ehi[i] = h;
    g_elo[i] = tf32_rnd(v - h);

    float s = v * v;
    #pragma unroll
    for (int off = 16; off; off >>= 1) s += __shfl_down_sync(0xffffffffu, s, off);
    __shared__ float ws[8];
    if ((d & 31) == 0) ws[d >> 5] = s;
    __syncthreads();
    if (d == 0) {
        float t = 0.f;
        #pragma unroll
        for (int i2 = 0; i2 < 8; i2++) t += ws[i2];
        g_embsq[k] = t;
    }
}

// ---------------- kernel 2: mma.sync tf32 distance GEMM + argmin ----------------
// 128 CTAs x 512 threads (16 warps). CTA: M=128 rows; 32 chunks of N=256 codes;
// K in 8 slabs of 32, cp.async double-buffered. Warp grid 2m x 8n, tile 64x32.
// acc = 4x4x4 = 64 regs/thread -> no spills; 4 warps/SMSP for latency hiding.
#define NCHUNK   256
#define NSLABS   8
#define NCHUNKS  (KCODES / NCHUNK)    // 32
#define GTOT     (NCHUNKS * NSLABS)   // 256
#define RS       36                   // smem row stride in floats (conflict-free)
#define A_F      (128 * RS)           // 4608 floats per A split
#define B_F      (NCHUNK * RS)        // 9216 floats per B split
#define BUF_F    (2 * A_F + 2 * B_F)  // 27648 floats = 110592 B per buffer
#define FOFF_AHI 0
#define FOFF_ALO A_F
#define FOFF_BHI (2 * A_F)
#define FOFF_BLO (2 * A_F + B_F)
#define NTHREADS 512

__global__ void __launch_bounds__(NTHREADS, 1)
argmin_kernel() {
    extern __shared__ float dsm[];
    __shared__ float s_minv[128][8];
    __shared__ int   s_mini[128][8];

    const int tid   = threadIdx.x;
    const int wid   = tid >> 5;
    const int lane  = tid & 31;
    const int qrow  = lane >> 2;     // 0..7
    const int qcol  = lane & 3;      // 0..3
    const int warpM = wid & 1;       // 2 row-groups (64 rows each)
    const int warpN = wid >> 1;      // 8 col-groups (32 cols each)
    const int rowBase = blockIdx.x * 128;

    const uint32_t dynb = smem_u32(dsm);

    // stage slab g into buffer g&1
    auto stage = [&](int g) {
        const uint32_t base = dynb + (uint32_t)(g & 1) * (BUF_F * 4);
        const int ks = g & 7, ch = g >> 3;
        const float* xh = g_xhi + (long)rowBase * DDIM + ks * 32;
        const float* xl = g_xlo + (long)rowBase * DDIM + ks * 32;
        const float* eh = g_ehi + (long)ch * NCHUNK * DDIM + ks * 32;
        const float* el = g_elo + (long)ch * NCHUNK * DDIM + ks * 32;
        #pragma unroll
        for (int i = tid; i < 1024; i += NTHREADS) {   // A: 128 rows x 8 seg
            int r = i >> 3, sg = i & 7;
            uint32_t o = (uint32_t)(r * RS + sg * 4) * 4;
            cpa16(base + FOFF_AHI * 4 + o, xh + (long)r * DDIM + sg * 4);
            cpa16(base + FOFF_ALO * 4 + o, xl + (long)r * DDIM + sg * 4);
        }
        #pragma unroll
        for (int i = tid; i < 2048; i += NTHREADS) {   // B: 256 rows x 8 seg
            int r = i >> 3, sg = i & 7;
            uint32_t o = (uint32_t)(r * RS + sg * 4) * 4;
            cpa16(base + FOFF_BHI * 4 + o, eh + (long)r * DDIM + sg * 4);
            cpa16(base + FOFF_BLO * 4 + o, el + (long)r * DDIM + sg * 4);
        }
    };

    stage(0);
    cpa_commit();

    float acc[4][4][4];     // [mt][nt][frag] -> 64 regs
    #pragma unroll
    for (int mt = 0; mt < 4; mt++)
        #pragma unroll
        for (int nt = 0; nt < 4; nt++)
            #pragma unroll
            for (int f = 0; f < 4; f++) acc[mt][nt][f] = 0.f;

    float minv[8];
    int   mini[8];
    #pragma unroll
    for (int s = 0; s < 8; s++) { minv[s] = 3.4e38f; mini[s] = 0; }

    for (int g = 0; g < GTOT; g++) {
        if (g + 1 < GTOT) { stage(g + 1); cpa_commit(); cpa_wait1(); }
        else              { cpa_wait0(); }
        __syncthreads();

        const float* buf = dsm + (g & 1) * BUF_F;
        const uint32_t* Ah = (const uint32_t*)(buf + FOFF_AHI);
        const uint32_t* Al = (const uint32_t*)(buf + FOFF_ALO);
        const uint32_t* Bh = (const uint32_t*)(buf + FOFF_BHI);
        const uint32_t* Bl = (const uint32_t*)(buf + FOFF_BLO);

        #pragma unroll
        for (int k8 = 0; k8 < 4; k8++) {
            const int kk = k8 * 8;
            uint32_t ah[4][4], al[4][4], bh[4][2];
            #pragma unroll
            for (int mt = 0; mt < 4; mt++) {
                int ra = (warpM * 64 + mt * 16 + qrow) * RS + kk + qcol;
                ah[mt][0] = Ah[ra];            ah[mt][1] = Ah[ra + 8 * RS];
                ah[mt][2] = Ah[ra + 4];        ah[mt][3] = Ah[ra + 8 * RS + 4];
                al[mt][0] = Al[ra];            al[mt][1] = Al[ra + 8 * RS];
                al[mt][2] = Al[ra + 4];        al[mt][3] = Al[ra + 8 * RS + 4];
            }
            #pragma unroll
            for (int nt = 0; nt < 4; nt++) {
                int rb = (warpN * 32 + nt * 8 + qrow) * RS + kk + qcol;
                bh[nt][0] = Bh[rb];
                bh[nt][1] = Bh[rb + 4];
            }
            // split 0: hi x hi
            #pragma unroll
            for (int nt = 0; nt < 4; nt++)
                #pragma unroll
                for (int mt = 0; mt < 4; mt++)
                    mma16n8k8(acc[mt][nt], ah[mt][0], ah[mt][1], ah[mt][2], ah[mt][3],
                              bh[nt][0], bh[nt][1]);
            // split 1: lo x hi
            #pragma unroll
            for (int nt = 0; nt < 4; nt++)
                #pragma unroll
                for (int mt = 0; mt < 4; mt++)
                    mma16n8k8(acc[mt][nt], al[mt][0], al[mt][1], al[mt][2], al[mt][3],
                              bh[nt][0], bh[nt][1]);
            // split 2: hi x lo
            #pragma unroll
            for (int nt = 0; nt < 4; nt++) {
                int rb = (warpN * 32 + nt * 8 + qrow) * RS + kk + qcol;
                uint32_t bl0 = Bl[rb], bl1 = Bl[rb + 4];
                #pragma unroll
                for (int mt = 0; mt < 4; mt++)
                    mma16n8k8(acc[mt][nt], ah[mt][0], ah[mt][1], ah[mt][2], ah[mt][3],
                              bl0, bl1);
            }
        }

        if ((g & 7) == 7) {       // chunk complete: fold into running argmin
            const int chunk = g >> 3;
            #pragma unroll
            for (int nt = 0; nt < 4; nt++) {
                int col0 = chunk * NCHUNK + warpN * 32 + nt * 8 + 2 * qcol;
                float e0 = g_embsq[col0];
                float e1 = g_embsq[col0 + 1];
                #pragma unroll
                for (int mt = 0; mt < 4; mt++) {
                    float d0 = fmaf(-2.f, acc[mt][nt][0], e0);
                    float d1 = fmaf(-2.f, acc[mt][nt][1], e1);
                    float d2 = fmaf(-2.f, acc[mt][nt][2], e0);
                    float d3 = fmaf(-2.f, acc[mt][nt][3], e1);
                    int s0 = mt * 2, s1 = mt * 2 + 1;
                    if (d0 < minv[s0]) { minv[s0] = d0; mini[s0] = col0; }
                    if (d1 < minv[s0]) { minv[s0] = d1; mini[s0] = col0 + 1; }
                    if (d2 < minv[s1]) { minv[s1] = d2; mini[s1] = col0; }
                    if (d3 < minv[s1]) { minv[s1] = d3; mini[s1] = col0 + 1; }
                    acc[mt][nt][0] = 0.f; acc[mt][nt][1] = 0.f;
                    acc[mt][nt][2] = 0.f; acc[mt][nt][3] = 0.f;
                }
            }
        }
        __syncthreads();
    }

    // reduce: quad (lanes sharing a row) then across 8 warpN groups via smem
    #pragma unroll
    for (int mt = 0; mt < 4; mt++)
        #pragma unroll
        for (int h = 0; h < 2; h++) {
            int s = mt * 2 + h;
            float v = minv[s];
            int   idx = mini[s];
            #pragma unroll
            for (int off = 1; off <= 2; off <<= 1) {
                float ov = __shfl_xor_sync(0xffffffffu, v, off);
                int   oi = __shfl_xor_sync(0xffffffffu, idx, off);
                if (ov < v || (ov == v && oi < idx)) { v = ov; idx = oi; }
            }
            if (qcol == 0) {
                int row = warpM * 64 + mt * 16 + h * 8 + qrow;
                s_minv[row][warpN] = v;
                s_mini[row][warpN] = idx;
            }
        }
    __syncthreads();
    if (tid < 128) {
        float bv = s_minv[tid][0];
        int   bi = s_mini[tid][0];
        #pragma unroll
        for (int n = 1; n < 8; n++) {
            float v = s_minv[tid][n];
            int   i = s_mini[tid][n];
            if (v < bv || (v == bv && i < bi)) { bv = v; bi = i; }
        }
        g_idx[rowBase + tid] = bi;
    }
}

// ---------------- kernel 3: gather quantized, loss, scatter EMA stats ----------------
__global__ void gather_kernel(const float* __restrict__ x, float* __restrict__ out) {
    int row = blockIdx.x;
    int d = threadIdx.x;
    int idx = g_idx[row];
    float xv = x[(long)row * DDIM + d];
    float qv = g_emb[(long)idx * DDIM + d];
    out[OFF_Q + (long)row * DDIM + d] = qv;

    float diff = qv - xv;
    float s = diff * diff;
    #pragma unroll
    for (int off = 16; off; off >>= 1) s += __shfl_down_sync(0xffffffffu, s, off);
    __shared__ float ws[8];
    if ((d & 31) == 0) ws[d >> 5] = s;
    __syncthreads();
    if (d == 0) {
        float t = 0.f;
        #pragma unroll
        for (int i = 0; i < 8; i++) t += ws[i];
        atomicAdd(&g_loss, t);
        atomicAdd(&g_counts[idx], 1.0f);
        out[OFF_IDX + row] = (float)idx;
    }
    atomicAdd(&g_dw[(long)idx * DDIM + d], xv);
}

// ---------------- kernel 4a: new_cluster_size + sum n ----------------
__global__ void cs_kernel(const float* __restrict__ cluster_size, float* __restrict__ out) {
    int k = blockIdx.x * 256 + threadIdx.x;
    float ncs = cluster_size[k] * DECAY + ONE_M_DECAY * g_counts[k];
    out[OFF_CS + k] = ncs;
    float s = ncs;
    #pragma unroll
    for (int off = 16; off; off >>= 1) s += __shfl_down_sync(0xffffffffu, s, off);
    __shared__ float ws[8];
    if ((threadIdx.x & 31) == 0) ws[threadIdx.x >> 5] = s;
    __syncthreads();
    if (threadIdx.x == 0) {
        float t = 0.f;
        #pragma unroll
        for (int i = 0; i < 8; i++) t += ws[i];
        atomicAdd(&g_nsum, t);
    }
}

// ---------------- kernel 4b: new_ema_w ----------------
__global__ void emaw_kernel(const float* __restrict__ ema_w, float* __restrict__ out) {
    long i = (long)blockIdx.x * blockDim.x + threadIdx.x;
    if (i < (long)KCODES * DDIM)
        out[OFF_EMAW + i] = ema_w[i] * DECAY + ONE_M_DECAY * g_dw[i];
}

// ---------------- kernel 5: smoothed normalize + loss write ----------------
__global__ void final_kernel(float* __restrict__ out) {
    int k = blockIdx.x;
    int d = threadIdx.x;
    float n = g_nsum;
    float ncs = out[OFF_CS + k];
    float smoothed = (ncs + EPSV) / (n + (float)KCODES * EPSV) * n;
    out[OFF_EMB + (long)k * DDIM + d] = out[OFF_EMAW + (long)k * DDIM + d] / smoothed;
    if (k == 0 && d == 0)
        out[OFF_LOSS] = 2.0f * g_loss / (float)((long)NROWS * DDIM);
}

// ---------------- launch ----------------
extern "C" void kernel_launch(void* const* d_in, const int* in_sizes, int n_in,
                              void* d_out, int out_size) {
    const float* x         = (const float*)d_in[0];
    const float* embedding = (const float*)d_in[1];
    const float* amean     = (const float*)d_in[2];
    const float* astd      = (const float*)d_in[3];
    const float* cs        = (const float*)d_in[4];
    const float* ema_w     = (const float*)d_in[5];
    float* out = (float*)d_out;

    (void)in_sizes; (void)n_in; (void)out_size;

    cudaFuncSetAttribute(argmin_kernel, cudaFuncAttributeMaxDynamicSharedMemorySize,
                         2 * BUF_F * 4);

    zero_kernel<<<2048, 256>>>();
    xsplit_kernel<<<NROWS * DDIM / 256, 256>>>(x);
    prep_kernel<<<KCODES, 256>>>(embedding, amean, astd);
    argmin_kernel<<<NROWS / 128, NTHREADS, 2 * BUF_F * 4>>>();
    gather_kernel<<<NROWS, 256>>>(x, out);
    cs_kernel<<<KCODES / 256, 256>>>(cs, out);
    emaw_kernel<<<(KCODES * DDIM + 255) / 256, 256>>>(ema_w, out);
    final_kernel<<<KCODES, 256>>>(out);
}

// round 11
// speedup vs baseline: 1.9719x; 1.8665x over previous
#include <cuda_runtime.h>
#include <cuda_fp16.h>
#include <cstdint>

// ---------------- problem constants ----------------
#define NROWS   16384
#define DDIM    256
#define KCODES  8192
#define DECAY   0.99f
#define ONE_M_DECAY 0.01f
#define EPSV    1e-5f

// output layout (concatenated, float32, tuple order)
#define OFF_Q     0L
#define OFF_LOSS  4194304L
#define OFF_IDX   4194305L
#define OFF_CS    4210689L
#define OFF_EMAW  4218881L
#define OFF_EMB   6316033L

// ---------------- scratch ----------------
__device__ float g_emb [KCODES * DDIM];
__device__ __align__(16) __half g_eh [KCODES * DDIM];
__device__ __align__(16) __half g_el [KCODES * DDIM];
__device__ __align__(16) __half g_xh [NROWS * DDIM];
__device__ __align__(16) __half g_xl [NROWS * DDIM];
__device__ float g_embsq[KCODES];
__device__ int   g_idx [NROWS];
__device__ float g_counts[KCODES];
__device__ float g_dw  [KCODES * DDIM];
__device__ float g_loss;
__device__ float g_nsum;

// ---------------- helpers ----------------
__device__ __forceinline__ void cpa16(uint32_t dst, const void* src) {
    asm volatile("cp.async.cg.shared.global [%0], [%1], 16;" :: "r"(dst), "l"(src));
}
__device__ __forceinline__ void cpa_commit() { asm volatile("cp.async.commit_group;"); }
__device__ __forceinline__ void cpa_wait1()  { asm volatile("cp.async.wait_group 1;" ::: "memory"); }
__device__ __forceinline__ void cpa_wait0()  { asm volatile("cp.async.wait_group 0;" ::: "memory"); }
__device__ __forceinline__ uint32_t smem_u32(const void* p) {
    uint32_t a;
    asm("{ .reg .u64 t; cvta.to.shared.u64 t, %1; cvt.u32.u64 %0, t; }" : "=r"(a) : "l"(p));
    return a;
}
__device__ __forceinline__ uint32_t ld32(const uint16_t* p) {
    return *reinterpret_cast<const uint32_t*>(p);
}
__device__ __forceinline__ void mma_f16(float c[4],
                                        uint32_t a0, uint32_t a1, uint32_t a2, uint32_t a3,
                                        uint32_t b0, uint32_t b1) {
    asm volatile(
        "mma.sync.aligned.m16n8k16.row.col.f32.f16.f16.f32 "
        "{%0,%1,%2,%3}, {%4,%5,%6,%7}, {%8,%9}, {%0,%1,%2,%3};"
        : "+f"(c[0]), "+f"(c[1]), "+f"(c[2]), "+f"(c[3])
        : "r"(a0), "r"(a1), "r"(a2), "r"(a3), "r"(b0), "r"(b1));
}

// ---------------- kernel 0: zero scratch ----------------
__global__ void zero_kernel() {
    long total = (long)KCODES * DDIM + KCODES + 2;
    for (long i = (long)blockIdx.x * blockDim.x + threadIdx.x; i < total;
         i += (long)gridDim.x * blockDim.x) {
        if (i < (long)KCODES * DDIM)               g_dw[i] = 0.f;
        else if (i < (long)KCODES * DDIM + KCODES) g_counts[i - (long)KCODES * DDIM] = 0.f;
        else if (i == (long)KCODES * DDIM + KCODES) g_loss = 0.f;
        else                                        g_nsum = 0.f;
    }
}

// ---------------- kernel 1a: split x into fp16 hi/lo ----------------
__global__ void xsplit_kernel(const float* __restrict__ x) {
    long i = (long)blockIdx.x * 256 + threadIdx.x;
    float v = x[i];
    __half h = __float2half(v);
    g_xh[i] = h;
    g_xl[i] = __float2half(v - __half2float(h));
}

// ---------------- kernel 1b: affine codebook + fp16 split + norms ----------------
__global__ void prep_kernel(const float* __restrict__ embedding,
                            const float* __restrict__ amean,
                            const float* __restrict__ astd) {
    int k = blockIdx.x;
    int d = threadIdx.x;
    long i = (long)k * DDIM + d;
    float v = amean[d] + astd[d] * embedding[i];
    g_emb[i] = v;
    __half h = __float2half(v);
    g_eh[i] = h;
    g_el[i] = __float2half(v - __half2float(h));

    float s = v * v;
    #pragma unroll
    for (int off = 16; off; off >>= 1) s += __shfl_down_sync(0xffffffffu, s, off);
    __shared__ float ws[8];
    if ((d & 31) == 0) ws[d >> 5] = s;
    __syncthreads();
    if (d == 0) {
        float t = 0.f;
        #pragma unroll
        for (int i2 = 0; i2 < 8; i2++) t += ws[i2];
        g_embsq[k] = t;
    }
}

// ---------------- kernel 2: mma.sync fp16 distance GEMM + argmin ----------------
// 128 CTAs x 512 threads (16 warps). CTA: M=128 rows; 32 chunks of N=256 codes;
// K in 4 slabs of 64 fp16, cp.async double-buffered. Warp grid 2m x 8n, tile 64x32.
// 3-split fp16 (hi*hi + hi*lo + lo*hi) on m16n8k16: half the MMA instr of tf32 k8.
#define NCHUNK   256
#define NSLABS   4                    // K=256 in slabs of 64
#define NCHUNKS  (KCODES / NCHUNK)    // 32
#define GTOT     (NCHUNKS * NSLABS)   // 128
#define RSU      72                   // smem row stride in u16 (64 fp16 + 8 pad)
#define A_U      (128 * RSU)          // 9216 u16 per A split
#define B_U      (NCHUNK * RSU)       // 18432 u16 per B split
#define BUF_U    (2 * A_U + 2 * B_U)  // 55296 u16 = 110592 B per buffer
#define UOFF_AHI 0
#define UOFF_ALO A_U
#define UOFF_BHI (2 * A_U)
#define UOFF_BLO (2 * A_U + B_U)
#define NTHREADS 512

__global__ void __launch_bounds__(NTHREADS, 1)
argmin_kernel() {
    extern __shared__ uint16_t dsmu[];
    __shared__ float s_minv[128][8];
    __shared__ int   s_mini[128][8];

    const int tid   = threadIdx.x;
    const int wid   = tid >> 5;
    const int lane  = tid & 31;
    const int qrow  = lane >> 2;     // 0..7
    const int qcol  = lane & 3;      // 0..3
    const int warpM = wid & 1;       // 2 row-groups (64 rows each)
    const int warpN = wid >> 1;      // 8 col-groups (32 cols each)
    const int rowBase = blockIdx.x * 128;

    const uint32_t dynb = smem_u32(dsmu);

    // stage slab g (K columns ks*64 .. +64) into buffer g&1
    auto stage = [&](int g) {
        const uint32_t base = dynb + (uint32_t)(g & 1) * (BUF_U * 2);
        const int ks = g & 3, ch = g >> 2;
        const __half* xh = g_xh + (long)rowBase * DDIM + ks * 64;
        const __half* xl = g_xl + (long)rowBase * DDIM + ks * 64;
        const __half* eh = g_eh + (long)ch * NCHUNK * DDIM + ks * 64;
        const __half* el = g_el + (long)ch * NCHUNK * DDIM + ks * 64;
        #pragma unroll
        for (int i = tid; i < 1024; i += NTHREADS) {   // A: 128 rows x 8 segs(16B)
            int r = i >> 3, sg = i & 7;
            uint32_t o = (uint32_t)(r * RSU + sg * 8) * 2;
            cpa16(base + UOFF_AHI * 2 + o, xh + (long)r * DDIM + sg * 8);
            cpa16(base + UOFF_ALO * 2 + o, xl + (long)r * DDIM + sg * 8);
        }
        #pragma unroll
        for (int i = tid; i < 2048; i += NTHREADS) {   // B: 256 rows x 8 segs
            int r = i >> 3, sg = i & 7;
            uint32_t o = (uint32_t)(r * RSU + sg * 8) * 2;
            cpa16(base + UOFF_BHI * 2 + o, eh + (long)r * DDIM + sg * 8);
            cpa16(base + UOFF_BLO * 2 + o, el + (long)r * DDIM + sg * 8);
        }
    };

    stage(0);
    cpa_commit();

    float acc[4][4][4];     // [mt][nt][frag] -> 64 regs
    #pragma unroll
    for (int mt = 0; mt < 4; mt++)
        #pragma unroll
        for (int nt = 0; nt < 4; nt++)
            #pragma unroll
            for (int f = 0; f < 4; f++) acc[mt][nt][f] = 0.f;

    float minv[8];
    int   mini[8];
    #pragma unroll
    for (int s = 0; s < 8; s++) { minv[s] = 3.4e38f; mini[s] = 0; }

    for (int g = 0; g < GTOT; g++) {
        if (g + 1 < GTOT) { stage(g + 1); cpa_commit(); cpa_wait1(); }
        else              { cpa_wait0(); }
        __syncthreads();

        const uint16_t* buf = dsmu + (g & 1) * BUF_U;
        const uint16_t* Ah = buf + UOFF_AHI;
        const uint16_t* Al = buf + UOFF_ALO;
        const uint16_t* Bh = buf + UOFF_BHI;
        const uint16_t* Bl = buf + UOFF_BLO;

        #pragma unroll
        for (int ks16 = 0; ks16 < 4; ks16++) {        // 4 k16-steps per 64-slab
            const int kk = ks16 * 16;
            uint32_t ah[4][4], al[4][4], bh[4][2];
            #pragma unroll
            for (int mt = 0; mt < 4; mt++) {
                int ra = (warpM * 64 + mt * 16 + qrow) * RSU + kk + 2 * qcol;
                ah[mt][0] = ld32(Ah + ra);             ah[mt][1] = ld32(Ah + ra + 8 * RSU);
                ah[mt][2] = ld32(Ah + ra + 8);         ah[mt][3] = ld32(Ah + ra + 8 * RSU + 8);
                al[mt][0] = ld32(Al + ra);             al[mt][1] = ld32(Al + ra + 8 * RSU);
                al[mt][2] = ld32(Al + ra + 8);         al[mt][3] = ld32(Al + ra + 8 * RSU + 8);
            }
            #pragma unroll
            for (int nt = 0; nt < 4; nt++) {
                int rb = (warpN * 32 + nt * 8 + qrow) * RSU + kk + 2 * qcol;
                bh[nt][0] = ld32(Bh + rb);
                bh[nt][1] = ld32(Bh + rb + 8);
            }
            // split 0: hi x hi
            #pragma unroll
            for (int nt = 0; nt < 4; nt++)
                #pragma unroll
                for (int mt = 0; mt < 4; mt++)
                    mma_f16(acc[mt][nt], ah[mt][0], ah[mt][1], ah[mt][2], ah[mt][3],
                            bh[nt][0], bh[nt][1]);
            // split 1: lo x hi
            #pragma unroll
            for (int nt = 0; nt < 4; nt++)
                #pragma unroll
                for (int mt = 0; mt < 4; mt++)
                    mma_f16(acc[mt][nt], al[mt][0], al[mt][1], al[mt][2], al[mt][3],
                            bh[nt][0], bh[nt][1]);
            // split 2: hi x lo
            #pragma unroll
            for (int nt = 0; nt < 4; nt++) {
                int rb = (warpN * 32 + nt * 8 + qrow) * RSU + kk + 2 * qcol;
                uint32_t bl0 = ld32(Bl + rb), bl1 = ld32(Bl + rb + 8);
                #pragma unroll
                for (int mt = 0; mt < 4; mt++)
                    mma_f16(acc[mt][nt], ah[mt][0], ah[mt][1], ah[mt][2], ah[mt][3],
                            bl0, bl1);
            }
        }

        if ((g & 3) == 3) {       // chunk complete: fold into running argmin
            const int chunk = g >> 2;
            #pragma unroll
            for (int nt = 0; nt < 4; nt++) {
                int col0 = chunk * NCHUNK + warpN * 32 + nt * 8 + 2 * qcol;
                float e0 = g_embsq[col0];
                float e1 = g_embsq[col0 + 1];
                #pragma unroll
                for (int mt = 0; mt < 4; mt++) {
                    float d0 = fmaf(-2.f, acc[mt][nt][0], e0);
                    float d1 = fmaf(-2.f, acc[mt][nt][1], e1);
                    float d2 = fmaf(-2.f, acc[mt][nt][2], e0);
                    float d3 = fmaf(-2.f, acc[mt][nt][3], e1);
                    int s0 = mt * 2, s1 = mt * 2 + 1;
                    if (d0 < minv[s0]) { minv[s0] = d0; mini[s0] = col0; }
                    if (d1 < minv[s0]) { minv[s0] = d1; mini[s0] = col0 + 1; }
                    if (d2 < minv[s1]) { minv[s1] = d2; mini[s1] = col0; }
                    if (d3 < minv[s1]) { minv[s1] = d3; mini[s1] = col0 + 1; }
                    acc[mt][nt][0] = 0.f; acc[mt][nt][1] = 0.f;
                    acc[mt][nt][2] = 0.f; acc[mt][nt][3] = 0.f;
                }
            }
        }
        __syncthreads();
    }

    // reduce: quad (lanes sharing a row) then across 8 warpN groups via smem
    #pragma unroll
    for (int mt = 0; mt < 4; mt++)
        #pragma unroll
        for (int h = 0; h < 2; h++) {
            int s = mt * 2 + h;
            float v = minv[s];
            int   idx = mini[s];
            #pragma unroll
            for (int off = 1; off <= 2; off <<= 1) {
                float ov = __shfl_xor_sync(0xffffffffu, v, off);
                int   oi = __shfl_xor_sync(0xffffffffu, idx, off);
                if (ov < v || (ov == v && oi < idx)) { v = ov; idx = oi; }
            }
            if (qcol == 0) {
                int row = warpM * 64 + mt * 16 + h * 8 + qrow;
                s_minv[row][warpN] = v;
                s_mini[row][warpN] = idx;
            }
        }
    __syncthreads();
    if (tid < 128) {
        float bv = s_minv[tid][0];
        int   bi = s_mini[tid][0];
        #pragma unroll
        for (int n = 1; n < 8; n++) {
            float v = s_minv[tid][n];
            int   i = s_mini[tid][n];
            if (v < bv || (v == bv && i < bi)) { bv = v; bi = i; }
        }
        g_idx[rowBase + tid] = bi;
    }
}

// ---------------- kernel 3: gather quantized, loss, scatter EMA stats ----------------
__global__ void gather_kernel(const float* __restrict__ x, float* __restrict__ out) {
    int row = blockIdx.x;
    int d = threadIdx.x;
    int idx = g_idx[row];
    float xv = x[(long)row * DDIM + d];
    float qv = g_emb[(long)idx * DDIM + d];
    out[OFF_Q + (long)row * DDIM + d] = qv;

    float diff = qv - xv;
    float s = diff * diff;
    #pragma unroll
    for (int off = 16; off; off >>= 1) s += __shfl_down_sync(0xffffffffu, s, off);
    __shared__ float ws[8];
    if ((d & 31) == 0) ws[d >> 5] = s;
    __syncthreads();
    if (d == 0) {
        float t = 0.f;
        #pragma unroll
        for (int i = 0; i < 8; i++) t += ws[i];
        atomicAdd(&g_loss, t);
        atomicAdd(&g_counts[idx], 1.0f);
        out[OFF_IDX + row] = (float)idx;
    }
    atomicAdd(&g_dw[(long)idx * DDIM + d], xv);
}

// ---------------- kernel 4a: new_cluster_size + sum n ----------------
__global__ void cs_kernel(const float* __restrict__ cluster_size, float* __restrict__ out) {
    int k = blockIdx.x * 256 + threadIdx.x;
    float ncs = cluster_size[k] * DECAY + ONE_M_DECAY * g_counts[k];
    out[OFF_CS + k] = ncs;
    float s = ncs;
    #pragma unroll
    for (int off = 16; off; off >>= 1) s += __shfl_down_sync(0xffffffffu, s, off);
    __shared__ float ws[8];
    if ((threadIdx.x & 31) == 0) ws[threadIdx.x >> 5] = s;
    __syncthreads();
    if (threadIdx.x == 0) {
        float t = 0.f;
        #pragma unroll
        for (int i = 0; i < 8; i++) t += ws[i];
        atomicAdd(&g_nsum, t);
    }
}

// ---------------- kernel 4b: new_ema_w ----------------
__global__ void emaw_kernel(const float* __restrict__ ema_w, float* __restrict__ out) {
    long i = (long)blockIdx.x * blockDim.x + threadIdx.x;
    if (i < (long)KCODES * DDIM)
        out[OFF_EMAW + i] = ema_w[i] * DECAY + ONE_M_DECAY * g_dw[i];
}

// ---------------- kernel 5: smoothed normalize + loss write ----------------
__global__ void final_kernel(float* __restrict__ out) {
    int k = blockIdx.x;
    int d = threadIdx.x;
    float n = g_nsum;
    float ncs = out[OFF_CS + k];
    float smoothed = (ncs + EPSV) / (n + (float)KCODES * EPSV) * n;
    out[OFF_EMB + (long)k * DDIM + d] = out[OFF_EMAW + (long)k * DDIM + d] / smoothed;
    if (k == 0 && d == 0)
        out[OFF_LOSS] = 2.0f * g_loss / (float)((long)NROWS * DDIM);
}

// ---------------- launch ----------------
extern "C" void kernel_launch(void* const* d_in, const int* in_sizes, int n_in,
                              void* d_out, int out_size) {
    const float* x         = (const float*)d_in[0];
    const float* embedding = (const float*)d_in[1];
    const float* amean     = (const float*)d_in[2];
    const float* astd      = (const float*)d_in[3];
    const float* cs        = (const float*)d_in[4];
    const float* ema_w     = (const float*)d_in[5];
    float* out = (float*)d_out;

    (void)in_sizes; (void)n_in; (void)out_size;

    cudaFuncSetAttribute(argmin_kernel, cudaFuncAttributeMaxDynamicSharedMemorySize,
                         2 * BUF_U * 2);

    zero_kernel<<<2048, 256>>>();
    xsplit_kernel<<<NROWS * DDIM / 256, 256>>>(x);
    prep_kernel<<<KCODES, 256>>>(embedding, amean, astd);
    argmin_kernel<<<NROWS / 128, NTHREADS, 2 * BUF_U * 2>>>();
    gather_kernel<<<NROWS, 256>>>(x, out);
    cs_kernel<<<KCODES / 256, 256>>>(cs, out);
    emaw_kernel<<<(KCODES * DDIM + 255) / 256, 256>>>(ema_w, out);
    final_kernel<<<KCODES, 256>>>(out);
}

// round 12
// speedup vs baseline: 2.0503x; 1.0397x over previous
#include <cuda_runtime.h>
#include <cuda_fp16.h>
#include <cstdint>

// ---------------- problem constants ----------------
#define NROWS   16384
#define DDIM    256
#define KCODES  8192
#define DECAY   0.99f
#define ONE_M_DECAY 0.01f
#define EPSV    1e-5f

// output layout (concatenated, float32, tuple order)
#define OFF_Q     0L
#define OFF_LOSS  4194304L
#define OFF_IDX   4194305L
#define OFF_CS    4210689L
#define OFF_EMAW  4218881L
#define OFF_EMB   6316033L

// ---------------- scratch ----------------
__device__ float g_emb [KCODES * DDIM];
__device__ __align__(16) __half g_eh [KCODES * DDIM];
__device__ __align__(16) __half g_el [KCODES * DDIM];
__device__ __align__(16) __half g_xh [NROWS * DDIM];
__device__ __align__(16) __half g_xl [NROWS * DDIM];
__device__ float g_embsq[KCODES];
__device__ int   g_idx [NROWS];
__device__ float g_counts[KCODES];
__device__ float g_dw  [KCODES * DDIM];
__device__ float g_loss;
__device__ float g_nsum;

// ---------------- helpers ----------------
__device__ __forceinline__ void cpa16(uint32_t dst, const void* src) {
    asm volatile("cp.async.cg.shared.global [%0], [%1], 16;" :: "r"(dst), "l"(src));
}
__device__ __forceinline__ void cpa_commit() { asm volatile("cp.async.commit_group;"); }
__device__ __forceinline__ void cpa_wait1()  { asm volatile("cp.async.wait_group 1;" ::: "memory"); }
__device__ __forceinline__ void cpa_wait0()  { asm volatile("cp.async.wait_group 0;" ::: "memory"); }
__device__ __forceinline__ uint32_t smem_u32(const void* p) {
    uint32_t a;
    asm("{ .reg .u64 t; cvta.to.shared.u64 t, %1; cvt.u32.u64 %0, t; }" : "=r"(a) : "l"(p));
    return a;
}
__device__ __forceinline__ void ldsm4(uint32_t& r0, uint32_t& r1, uint32_t& r2, uint32_t& r3,
                                      uint32_t addr) {
    asm volatile("ldmatrix.sync.aligned.m8n8.x4.shared.b16 {%0,%1,%2,%3}, [%4];"
                 : "=r"(r0), "=r"(r1), "=r"(r2), "=r"(r3) : "r"(addr));
}
__device__ __forceinline__ void mma_f16(float c[4],
                                        uint32_t a0, uint32_t a1, uint32_t a2, uint32_t a3,
                                        uint32_t b0, uint32_t b1) {
    asm volatile(
        "mma.sync.aligned.m16n8k16.row.col.f32.f16.f16.f32 "
        "{%0,%1,%2,%3}, {%4,%5,%6,%7}, {%8,%9}, {%0,%1,%2,%3};"
        : "+f"(c[0]), "+f"(c[1]), "+f"(c[2]), "+f"(c[3])
        : "r"(a0), "r"(a1), "r"(a2), "r"(a3), "r"(b0), "r"(b1));
}

// ---------------- kernel 0: zero scratch ----------------
__global__ void zero_kernel() {
    long total = (long)KCODES * DDIM + KCODES + 2;
    for (long i = (long)blockIdx.x * blockDim.x + threadIdx.x; i < total;
         i += (long)gridDim.x * blockDim.x) {
        if (i < (long)KCODES * DDIM)               g_dw[i] = 0.f;
        else if (i < (long)KCODES * DDIM + KCODES) g_counts[i - (long)KCODES * DDIM] = 0.f;
        else if (i == (long)KCODES * DDIM + KCODES) g_loss = 0.f;
        else                                        g_nsum = 0.f;
    }
}

// ---------------- kernel 1a: split x into fp16 hi/lo ----------------
__global__ void xsplit_kernel(const float* __restrict__ x) {
    long i = (long)blockIdx.x * 256 + threadIdx.x;
    float v = x[i];
    __half h = __float2half(v);
    g_xh[i] = h;
    g_xl[i] = __float2half(v - __half2float(h));
}

// ---------------- kernel 1b: affine codebook + fp16 split + norms ----------------
__global__ void prep_kernel(const float* __restrict__ embedding,
                            const float* __restrict__ amean,
                            const float* __restrict__ astd) {
    int k = blockIdx.x;
    int d = threadIdx.x;
    long i = (long)k * DDIM + d;
    float v = amean[d] + astd[d] * embedding[i];
    g_emb[i] = v;
    __half h = __float2half(v);
    g_eh[i] = h;
    g_el[i] = __float2half(v - __half2float(h));

    float s = v * v;
    #pragma unroll
    for (int off = 16; off; off >>= 1) s += __shfl_down_sync(0xffffffffu, s, off);
    __shared__ float ws[8];
    if ((d & 31) == 0) ws[d >> 5] = s;
    __syncthreads();
    if (d == 0) {
        float t = 0.f;
        #pragma unroll
        for (int i2 = 0; i2 < 8; i2++) t += ws[i2];
        g_embsq[k] = t;
    }
}

// ---------------- kernel 2: mma.sync fp16 distance GEMM + argmin ----------------
// 128 CTAs x 512 threads (16 warps). CTA: M=128 rows; 32 chunks of N=256 codes;
// K in 4 slabs of 64 fp16, cp.async double-buffered. Warp grid 2m x 8n, tile 64x32.
// 3-split fp16 on m16n8k16; fragment loads via ldmatrix.x4 (12 vs 48 LDS per k16).
#define NCHUNK   256
#define NSLABS   4                    // K=256 in slabs of 64
#define NCHUNKS  (KCODES / NCHUNK)    // 32
#define GTOT     (NCHUNKS * NSLABS)   // 128
#define RSU      72                   // smem row stride in u16 (64 fp16 + 8 pad)
#define A_U      (128 * RSU)          // 9216 u16 per A split
#define B_U      (NCHUNK * RSU)       // 18432 u16 per B split
#define BUF_U    (2 * A_U + 2 * B_U)  // 55296 u16 = 110592 B per buffer
#define UOFF_AHI 0
#define UOFF_ALO A_U
#define UOFF_BHI (2 * A_U)
#define UOFF_BLO (2 * A_U + B_U)
#define NTHREADS 512

__global__ void __launch_bounds__(NTHREADS, 1)
argmin_kernel() {
    extern __shared__ uint16_t dsmu[];
    __shared__ float s_minv[128][8];
    __shared__ int   s_mini[128][8];

    const int tid   = threadIdx.x;
    const int wid   = tid >> 5;
    const int lane  = tid & 31;
    const int qrow  = lane >> 2;     // 0..7
    const int qcol  = lane & 3;      // 0..3
    const int warpM = wid & 1;       // 2 row-groups (64 rows each)
    const int warpN = wid >> 1;      // 8 col-groups (32 cols each)
    const int rowBase = blockIdx.x * 128;

    const uint32_t dynb = smem_u32(dsmu);

    // per-lane ldmatrix row offsets (u16 units, kk/mt/p added per use)
    // A x4: m0 rows0-7/k0-7, m1 rows8-15/k0-7, m2 rows0-7/k8-15, m3 rows8-15/k8-15
    const uint32_t a_off = (uint32_t)((warpM * 64 + (lane & 7) + ((lane >> 3) & 1) * 8) * RSU
                                      + ((lane >> 4) & 1) * 8);
    // B x4: m0 nt(2p) k0-7 -> b0, m1 nt(2p) k8-15 -> b1, m2/m3 same for nt(2p+1)
    const uint32_t b_off = (uint32_t)((warpN * 32 + (lane & 7) + ((lane >> 4) & 1) * 8) * RSU
                                      + ((lane >> 3) & 1) * 8);

    // stage slab g (K columns ks*64 .. +64) into buffer g&1
    auto stage = [&](int g) {
        const uint32_t base = dynb + (uint32_t)(g & 1) * (BUF_U * 2);
        const int ks = g & 3, ch = g >> 2;
        const __half* xh = g_xh + (long)rowBase * DDIM + ks * 64;
        const __half* xl = g_xl + (long)rowBase * DDIM + ks * 64;
        const __half* eh = g_eh + (long)ch * NCHUNK * DDIM + ks * 64;
        const __half* el = g_el + (long)ch * NCHUNK * DDIM + ks * 64;
        #pragma unroll
        for (int i = tid; i < 1024; i += NTHREADS) {   // A: 128 rows x 8 segs(16B)
            int r = i >> 3, sg = i & 7;
            uint32_t o = (uint32_t)(r * RSU + sg * 8) * 2;
            cpa16(base + UOFF_AHI * 2 + o, xh + (long)r * DDIM + sg * 8);
            cpa16(base + UOFF_ALO * 2 + o, xl + (long)r * DDIM + sg * 8);
        }
        #pragma unroll
        for (int i = tid; i < 2048; i += NTHREADS) {   // B: 256 rows x 8 segs
            int r = i >> 3, sg = i & 7;
            uint32_t o = (uint32_t)(r * RSU + sg * 8) * 2;
            cpa16(base + UOFF_BHI * 2 + o, eh + (long)r * DDIM + sg * 8);
            cpa16(base + UOFF_BLO * 2 + o, el + (long)r * DDIM + sg * 8);
        }
    };

    stage(0);
    cpa_commit();

    float acc[4][4][4];     // [mt][nt][frag] -> 64 regs
    #pragma unroll
    for (int mt = 0; mt < 4; mt++)
        #pragma unroll
        for (int nt = 0; nt < 4; nt++)
            #pragma unroll
            for (int f = 0; f < 4; f++) acc[mt][nt][f] = 0.f;

    float minv[8];
    int   mini[8];
    #pragma unroll
    for (int s = 0; s < 8; s++) { minv[s] = 3.4e38f; mini[s] = 0; }

    for (int g = 0; g < GTOT; g++) {
        if (g + 1 < GTOT) { stage(g + 1); cpa_commit(); cpa_wait1(); }
        else              { cpa_wait0(); }
        __syncthreads();

        const uint32_t base = dynb + (uint32_t)(g & 1) * (BUF_U * 2);
        const uint32_t baseAh = base + UOFF_AHI * 2;
        const uint32_t baseAl = base + UOFF_ALO * 2;
        const uint32_t baseBh = base + UOFF_BHI * 2;
        const uint32_t baseBl = base + UOFF_BLO * 2;

        #pragma unroll
        for (int ks16 = 0; ks16 < 4; ks16++) {        // 4 k16-steps per 64-slab
            const uint32_t kk = (uint32_t)(ks16 * 16);
            uint32_t ah[4][4], bh[4][2];
            #pragma unroll
            for (int mt = 0; mt < 4; mt++)
                ldsm4(ah[mt][0], ah[mt][1], ah[mt][2], ah[mt][3],
                      baseAh + (uint32_t)(mt * 16 * RSU + kk + a_off) * 2);
            #pragma unroll
            for (int p = 0; p < 2; p++)
                ldsm4(bh[2*p][0], bh[2*p][1], bh[2*p+1][0], bh[2*p+1][1],
                      baseBh + (uint32_t)(p * 16 * RSU + kk + b_off) * 2);
            // split 0: hi x hi
            #pragma unroll
            for (int nt = 0; nt < 4; nt++)
                #pragma unroll
                for (int mt = 0; mt < 4; mt++)
                    mma_f16(acc[mt][nt], ah[mt][0], ah[mt][1], ah[mt][2], ah[mt][3],
                            bh[nt][0], bh[nt][1]);
            // split 1: lo x hi
            {
                uint32_t al[4][4];
                #pragma unroll
                for (int mt = 0; mt < 4; mt++)
                    ldsm4(al[mt][0], al[mt][1], al[mt][2], al[mt][3],
                          baseAl + (uint32_t)(mt * 16 * RSU + kk + a_off) * 2);
                #pragma unroll
                for (int nt = 0; nt < 4; nt++)
                    #pragma unroll
                    for (int mt = 0; mt < 4; mt++)
                        mma_f16(acc[mt][nt], al[mt][0], al[mt][1], al[mt][2], al[mt][3],
                                bh[nt][0], bh[nt][1]);
            }
            // split 2: hi x lo
            {
                uint32_t bl[4][2];
                #pragma unroll
                for (int p = 0; p < 2; p++)
                    ldsm4(bl[2*p][0], bl[2*p][1], bl[2*p+1][0], bl[2*p+1][1],
                          baseBl + (uint32_t)(p * 16 * RSU + kk + b_off) * 2);
                #pragma unroll
                for (int nt = 0; nt < 4; nt++)
                    #pragma unroll
                    for (int mt = 0; mt < 4; mt++)
                        mma_f16(acc[mt][nt], ah[mt][0], ah[mt][1], ah[mt][2], ah[mt][3],
                                bl[nt][0], bl[nt][1]);
            }
        }

        if ((g & 3) == 3) {       // chunk complete: fold into running argmin
            const int chunk = g >> 2;
            #pragma unroll
            for (int nt = 0; nt < 4; nt++) {
                int col0 = chunk * NCHUNK + warpN * 32 + nt * 8 + 2 * qcol;
                float e0 = g_embsq[col0];
                float e1 = g_embsq[col0 + 1];
                #pragma unroll
                for (int mt = 0; mt < 4; mt++) {
                    float d0 = fmaf(-2.f, acc[mt][nt][0], e0);
                    float d1 = fmaf(-2.f, acc[mt][nt][1], e1);
                    float d2 = fmaf(-2.f, acc[mt][nt][2], e0);
                    float d3 = fmaf(-2.f, acc[mt][nt][3], e1);
                    int s0 = mt * 2, s1 = mt * 2 + 1;
                    if (d0 < minv[s0]) { minv[s0] = d0; mini[s0] = col0; }
                    if (d1 < minv[s0]) { minv[s0] = d1; mini[s0] = col0 + 1; }
                    if (d2 < minv[s1]) { minv[s1] = d2; mini[s1] = col0; }
                    if (d3 < minv[s1]) { minv[s1] = d3; mini[s1] = col0 + 1; }
                    acc[mt][nt][0] = 0.f; acc[mt][nt][1] = 0.f;
                    acc[mt][nt][2] = 0.f; acc[mt][nt][3] = 0.f;
                }
            }
        }
        __syncthreads();
    }

    // reduce: quad (lanes sharing a row) then across 8 warpN groups via smem
    #pragma unroll
    for (int mt = 0; mt < 4; mt++)
        #pragma unroll
        for (int h = 0; h < 2; h++) {
            int s = mt * 2 + h;
            float v = minv[s];
            int   idx = mini[s];
            #pragma unroll
            for (int off = 1; off <= 2; off <<= 1) {
                float ov = __shfl_xor_sync(0xffffffffu, v, off);
                int   oi = __shfl_xor_sync(0xffffffffu, idx, off);
                if (ov < v || (ov == v && oi < idx)) { v = ov; idx = oi; }
            }
            if (qcol == 0) {
                int row = warpM * 64 + mt * 16 + h * 8 + qrow;
                s_minv[row][warpN] = v;
                s_mini[row][warpN] = idx;
            }
        }
    __syncthreads();
    if (tid < 128) {
        float bv = s_minv[tid][0];
        int   bi = s_mini[tid][0];
        #pragma unroll
        for (int n = 1; n < 8; n++) {
            float v = s_minv[tid][n];
            int   i = s_mini[tid][n];
            if (v < bv || (v == bv && i < bi)) { bv = v; bi = i; }
        }
        g_idx[rowBase + tid] = bi;
    }
}

// ---------------- kernel 3: gather quantized, loss, scatter EMA stats ----------------
__global__ void gather_kernel(const float* __restrict__ x, float* __restrict__ out) {
    int row = blockIdx.x;
    int d = threadIdx.x;
    int idx = g_idx[row];
    float xv = x[(long)row * DDIM + d];
    float qv = g_emb[(long)idx * DDIM + d];
    out[OFF_Q + (long)row * DDIM + d] = qv;

    float diff = qv - xv;
    float s = diff * diff;
    #pragma unroll
    for (int off = 16; off; off >>= 1) s += __shfl_down_sync(0xffffffffu, s, off);
    __shared__ float ws[8];
    if ((d & 31) == 0) ws[d >> 5] = s;
    __syncthreads();
    if (d == 0) {
        float t = 0.f;
        #pragma unroll
        for (int i = 0; i < 8; i++) t += ws[i];
        atomicAdd(&g_loss, t);
        atomicAdd(&g_counts[idx], 1.0f);
        out[OFF_IDX + row] = (float)idx;
    }
    atomicAdd(&g_dw[(long)idx * DDIM + d], xv);
}

// ---------------- kernel 4a: new_cluster_size + sum n ----------------
__global__ void cs_kernel(const float* __restrict__ cluster_size, float* __restrict__ out) {
    int k = blockIdx.x * 256 + threadIdx.x;
    float ncs = cluster_size[k] * DECAY + ONE_M_DECAY * g_counts[k];
    out[OFF_CS + k] = ncs;
    float s = ncs;
    #pragma unroll
    for (int off = 16; off; off >>= 1) s += __shfl_down_sync(0xffffffffu, s, off);
    __shared__ float ws[8];
    if ((threadIdx.x & 31) == 0) ws[threadIdx.x >> 5] = s;
    __syncthreads();
    if (threadIdx.x == 0) {
        float t = 0.f;
        #pragma unroll
        for (int i = 0; i < 8; i++) t += ws[i];
        atomicAdd(&g_nsum, t);
    }
}

// ---------------- kernel 4b: new_ema_w ----------------
__global__ void emaw_kernel(const float* __restrict__ ema_w, float* __restrict__ out) {
    long i = (long)blockIdx.x * blockDim.x + threadIdx.x;
    if (i < (long)KCODES * DDIM)
        out[OFF_EMAW + i] = ema_w[i] * DECAY + ONE_M_DECAY * g_dw[i];
}

// ---------------- kernel 5: smoothed normalize + loss write ----------------
__global__ void final_kernel(float* __restrict__ out) {
    int k = blockIdx.x;
    int d = threadIdx.x;
    float n = g_nsum;
    float ncs = out[OFF_CS + k];
    float smoothed = (ncs + EPSV) / (n + (float)KCODES * EPSV) * n;
    out[OFF_EMB + (long)k * DDIM + d] = out[OFF_EMAW + (long)k * DDIM + d] / smoothed;
    if (k == 0 && d == 0)
        out[OFF_LOSS] = 2.0f * g_loss / (float)((long)NROWS * DDIM);
}

// ---------------- launch ----------------
extern "C" void kernel_launch(void* const* d_in, const int* in_sizes, int n_in,
                              void* d_out, int out_size) {
    const float* x         = (const float*)d_in[0];
    const float* embedding = (const float*)d_in[1];
    const float* amean     = (const float*)d_in[2];
    const float* astd      = (const float*)d_in[3];
    const float* cs        = (const float*)d_in[4];
    const float* ema_w     = (const float*)d_in[5];
    float* out = (float*)d_out;

    (void)in_sizes; (void)n_in; (void)out_size;

    cudaFuncSetAttribute(argmin_kernel, cudaFuncAttributeMaxDynamicSharedMemorySize,
                         2 * BUF_U * 2);

    zero_kernel<<<2048, 256>>>();
    xsplit_kernel<<<NROWS * DDIM / 256, 256>>>(x);
    prep_kernel<<<KCODES, 256>>>(embedding, amean, astd);
    argmin_kernel<<<NROWS / 128, NTHREADS, 2 * BUF_U * 2>>>();
    gather_kernel<<<NROWS, 256>>>(x, out);
    cs_kernel<<<KCODES / 256, 256>>>(cs, out);
    emaw_kernel<<<(KCODES * DDIM + 255) / 256, 256>>>(ema_w, out);
    final_kernel<<<KCODES, 256>>>(out);
}

// round 15
// speedup vs baseline: 2.0830x; 1.0159x over previous
#include <cuda_runtime.h>
#include <cuda_fp16.h>
#include <cstdint>

// ---------------- problem constants ----------------
#define NROWS   16384
#define NROWS_PAD 16464               // 147 CTAs x 112 rows
#define DDIM    256
#define KCODES  8192
#define DECAY   0.99f
#define ONE_M_DECAY 0.01f
#define EPSV    1e-5f

// output layout (concatenated, float32, tuple order)
#define OFF_Q     0L
#define OFF_LOSS  4194304L
#define OFF_IDX   4194305L
#define OFF_CS    4210689L
#define OFF_EMAW  4218881L
#define OFF_EMB   6316033L

// ---------------- scratch ----------------
__device__ float g_emb [KCODES * DDIM];
__device__ __align__(16) __half g_eh [KCODES * DDIM];
__device__ __align__(16) __half g_el [KCODES * DDIM];
__device__ __align__(16) __half g_xh [NROWS_PAD * DDIM];   // pad rows stay zero
__device__ __align__(16) __half g_xl [NROWS_PAD * DDIM];
__device__ float g_embsq[KCODES];
__device__ int   g_idx [NROWS_PAD];
__device__ float g_counts[KCODES];
__device__ float g_dw  [KCODES * DDIM];
__device__ float g_loss;
__device__ float g_nsum;

// ---------------- helpers ----------------
__device__ __forceinline__ void cpa16(uint32_t dst, const void* src) {
    asm volatile("cp.async.cg.shared.global [%0], [%1], 16;" :: "r"(dst), "l"(src));
}
__device__ __forceinline__ void cpa_commit() { asm volatile("cp.async.commit_group;"); }
__device__ __forceinline__ void cpa_wait1()  { asm volatile("cp.async.wait_group 1;" ::: "memory"); }
__device__ __forceinline__ void cpa_wait0()  { asm volatile("cp.async.wait_group 0;" ::: "memory"); }
__device__ __forceinline__ uint32_t smem_u32(const void* p) {
    uint32_t a;
    asm("{ .reg .u64 t; cvta.to.shared.u64 t, %1; cvt.u32.u64 %0, t; }" : "=r"(a) : "l"(p));
    return a;
}
__device__ __forceinline__ void ldsm4(uint32_t& r0, uint32_t& r1, uint32_t& r2, uint32_t& r3,
                                      uint32_t addr) {
    asm volatile("ldmatrix.sync.aligned.m8n8.x4.shared.b16 {%0,%1,%2,%3}, [%4];"
                 : "=r"(r0), "=r"(r1), "=r"(r2), "=r"(r3) : "r"(addr));
}
__device__ __forceinline__ void mma_f16(float c[4],
                                        uint32_t a0, uint32_t a1, uint32_t a2, uint32_t a3,
                                        uint32_t b0, uint32_t b1) {
    asm volatile(
        "mma.sync.aligned.m16n8k16.row.col.f32.f16.f16.f32 "
        "{%0,%1,%2,%3}, {%4,%5,%6,%7}, {%8,%9}, {%0,%1,%2,%3};"
        : "+f"(c[0]), "+f"(c[1]), "+f"(c[2]), "+f"(c[3])
        : "r"(a0), "r"(a1), "r"(a2), "r"(a3), "r"(b0), "r"(b1));
}

// ---------------- kernel 0: zero scratch ----------------
__global__ void zero_kernel() {
    long total = (long)KCODES * DDIM + KCODES + 2;
    for (long i = (long)blockIdx.x * blockDim.x + threadIdx.x; i < total;
         i += (long)gridDim.x * blockDim.x) {
        if (i < (long)KCODES * DDIM)               g_dw[i] = 0.f;
        else if (i < (long)KCODES * DDIM + KCODES) g_counts[i - (long)KCODES * DDIM] = 0.f;
        else if (i == (long)KCODES * DDIM + KCODES) g_loss = 0.f;
        else                                        g_nsum = 0.f;
    }
}

// ---------------- kernel 1a: split x into fp16 hi/lo ----------------
__global__ void xsplit_kernel(const float* __restrict__ x) {
    long i = (long)blockIdx.x * 256 + threadIdx.x;
    float v = x[i];
    __half h = __float2half(v);
    g_xh[i] = h;
    g_xl[i] = __float2half(v - __half2float(h));
}

// ---------------- kernel 1b: affine codebook + fp16 split + norms ----------------
__global__ void prep_kernel(const float* __restrict__ embedding,
                            const float* __restrict__ amean,
                            const float* __restrict__ astd) {
    int k = blockIdx.x;
    int d = threadIdx.x;
    long i = (long)k * DDIM + d;
    float v = amean[d] + astd[d] * embedding[i];
    g_emb[i] = v;
    __half h = __float2half(v);
    g_eh[i] = h;
    g_el[i] = __float2half(v - __half2float(h));

    float s = v * v;
    #pragma unroll
    for (int off = 16; off; off >>= 1) s += __shfl_down_sync(0xffffffffu, s, off);
    __shared__ float ws[8];
    if ((d & 31) == 0) ws[d >> 5] = s;
    __syncthreads();
    if (d == 0) {
        float t = 0.f;
        #pragma unroll
        for (int i2 = 0; i2 < 8; i2++) t += ws[i2];
        g_embsq[k] = t;
    }
}

// ---------------- kernel 2: mma.sync fp16 distance GEMM + argmin ----------------
// 147 CTAs x 448 threads (14 warps, 7m x 2n). CTA: M=112 rows; 32 chunks of N=256;
// K in 4 slabs of 64 fp16, cp.async double-buffered. Warp tile 16x128 (mt=1, nt=16).
#define NCHUNK   256
#define NSLABS   4                    // K=256 in slabs of 64
#define NCHUNKS  (KCODES / NCHUNK)    // 32
#define GTOT     (NCHUNKS * NSLABS)   // 128
#define MROWS    112
#define RSU      72                   // smem row stride in u16 (64 fp16 + 8 pad)
#define A_U      (MROWS * RSU)        // 8064 u16 per A split
#define B_U      (NCHUNK * RSU)       // 18432 u16 per B split
#define BUF_U    (2 * A_U + 2 * B_U)  // 52992 u16 = 105984 B per buffer
#define UOFF_AHI 0
#define UOFF_ALO A_U
#define UOFF_BHI (2 * A_U)
#define UOFF_BLO (2 * A_U + B_U)
#define NTHREADS 448

__global__ void __launch_bounds__(NTHREADS, 1)
argmin_kernel() {
    extern __shared__ uint16_t dsmu[];
    __shared__ float s_minv[MROWS][2];
    __shared__ int   s_mini[MROWS][2];

    const int tid   = threadIdx.x;
    const int wid   = tid >> 5;      // 0..13
    const int lane  = tid & 31;
    const int qrow  = lane >> 2;     // 0..7
    const int qcol  = lane & 3;      // 0..3
    const int warpM = wid % 7;       // 7 row-groups (16 rows each)
    const int warpN = wid / 7;       // 2 col-groups (128 cols each)
    const int rowBase = blockIdx.x * MROWS;

    const uint32_t dynb = smem_u32(dsmu);

    // per-lane ldmatrix row offsets (u16 units)
    const uint32_t a_off = (uint32_t)((warpM * 16 + (lane & 7) + ((lane >> 3) & 1) * 8) * RSU
                                      + ((lane >> 4) & 1) * 8);
    const uint32_t b_off = (uint32_t)((warpN * 128 + (lane & 7) + ((lane >> 4) & 1) * 8) * RSU
                                      + ((lane >> 3) & 1) * 8);

    // stage slab g (K columns ks*64 .. +64) into buffer g&1
    auto stage = [&](int g) {
        const uint32_t base = dynb + (uint32_t)(g & 1) * (BUF_U * 2);
        const int ks = g & 3, ch = g >> 2;
        const __half* xh = g_xh + (long)rowBase * DDIM + ks * 64;
        const __half* xl = g_xl + (long)rowBase * DDIM + ks * 64;
        const __half* eh = g_eh + (long)ch * NCHUNK * DDIM + ks * 64;
        const __half* el = g_el + (long)ch * NCHUNK * DDIM + ks * 64;
        for (int i = tid; i < MROWS * 8; i += NTHREADS) {   // A: 112 rows x 8 segs
            int r = i >> 3, sg = i & 7;
            uint32_t o = (uint32_t)(r * RSU + sg * 8) * 2;
            cpa16(base + UOFF_AHI * 2 + o, xh + (long)r * DDIM + sg * 8);
            cpa16(base + UOFF_ALO * 2 + o, xl + (long)r * DDIM + sg * 8);
        }
        for (int i = tid; i < 2048; i += NTHREADS) {        // B: 256 rows x 8 segs
            int r = i >> 3, sg = i & 7;
            uint32_t o = (uint32_t)(r * RSU + sg * 8) * 2;
            cpa16(base + UOFF_BHI * 2 + o, eh + (long)r * DDIM + sg * 8);
            cpa16(base + UOFF_BLO * 2 + o, el + (long)r * DDIM + sg * 8);
        }
    };

    stage(0);
    cpa_commit();

    float acc[16][4];       // [nt][frag] -> 64 regs
    #pragma unroll
    for (int nt = 0; nt < 16; nt++)
        #pragma unroll
        for (int f = 0; f < 4; f++) acc[nt][f] = 0.f;

    float minv[2];
    int   mini[2];
    minv[0] = 3.4e38f; minv[1] = 3.4e38f; mini[0] = 0; mini[1] = 0;

    for (int g = 0; g < GTOT; g++) {
        if (g + 1 < GTOT) { stage(g + 1); cpa_commit(); cpa_wait1(); }
        else              { cpa_wait0(); }
        __syncthreads();

        const uint32_t base = dynb + (uint32_t)(g & 1) * (BUF_U * 2);
        const uint32_t baseAh = base + UOFF_AHI * 2;
        const uint32_t baseAl = base + UOFF_ALO * 2;
        const uint32_t baseBh = base + UOFF_BHI * 2;
        const uint32_t baseBl = base + UOFF_BLO * 2;

        #pragma unroll
        for (int ks16 = 0; ks16 < 4; ks16++) {        // 4 k16-steps per 64-slab
            const uint32_t kk = (uint32_t)(ks16 * 16);
            uint32_t ah[4], bh[16][2];
            ldsm4(ah[0], ah[1], ah[2], ah[3], baseAh + (kk + a_off) * 2);
            #pragma unroll
            for (int p = 0; p < 8; p++)
                ldsm4(bh[2*p][0], bh[2*p][1], bh[2*p+1][0], bh[2*p+1][1],
                      baseBh + (uint32_t)(p * 16 * RSU + kk + b_off) * 2);
            // split 0: hi x hi
            #pragma unroll
            for (int nt = 0; nt < 16; nt++)
                mma_f16(acc[nt], ah[0], ah[1], ah[2], ah[3], bh[nt][0], bh[nt][1]);
            // split 1: lo x hi
            {
                uint32_t al[4];
                ldsm4(al[0], al[1], al[2], al[3], baseAl + (kk + a_off) * 2);
                #pragma unroll
                for (int nt = 0; nt < 16; nt++)
                    mma_f16(acc[nt], al[0], al[1], al[2], al[3], bh[nt][0], bh[nt][1]);
            }
            // split 2: hi x lo
            {
                uint32_t bl[16][2];
                #pragma unroll
                for (int p = 0; p < 8; p++)
                    ldsm4(bl[2*p][0], bl[2*p][1], bl[2*p+1][0], bl[2*p+1][1],
                          baseBl + (uint32_t)(p * 16 * RSU + kk + b_off) * 2);
                #pragma unroll
                for (int nt = 0; nt < 16; nt++)
                    mma_f16(acc[nt], ah[0], ah[1], ah[2], ah[3], bl[nt][0], bl[nt][1]);
            }
        }

        if ((g & 3) == 3) {       // chunk complete: fold into running argmin
            const int chunk = g >> 2;
            #pragma unroll
            for (int nt = 0; nt < 16; nt++) {
                int col0 = chunk * NCHUNK + warpN * 128 + nt * 8 + 2 * qcol;
                float e0 = g_embsq[col0];
                float e1 = g_embsq[col0 + 1];
                float d0 = fmaf(-2.f, acc[nt][0], e0);
                float d1 = fmaf(-2.f, acc[nt][1], e1);
                float d2 = fmaf(-2.f, acc[nt][2], e0);
                float d3 = fmaf(-2.f, acc[nt][3], e1);
                if (d0 < minv[0]) { minv[0] = d0; mini[0] = col0; }
                if (d1 < minv[0]) { minv[0] = d1; mini[0] = col0 + 1; }
                if (d2 < minv[1]) { minv[1] = d2; mini[1] = col0; }
                if (d3 < minv[1]) { minv[1] = d3; mini[1] = col0 + 1; }
                acc[nt][0] = 0.f; acc[nt][1] = 0.f;
                acc[nt][2] = 0.f; acc[nt][3] = 0.f;
            }
        }
        __syncthreads();
    }

    // reduce: quad (lanes sharing a row) then across 2 warpN groups via smem
    #pragma unroll
    for (int h = 0; h < 2; h++) {
        float v = minv[h];
        int   idx = mini[h];
        #pragma unroll
        for (int off = 1; off <= 2; off <<= 1) {
            float ov = __shfl_xor_sync(0xffffffffu, v, off);
            int   oi = __shfl_xor_sync(0xffffffffu, idx, off);
            if (ov < v || (ov == v && oi < idx)) { v = ov; idx = oi; }
        }
        if (qcol == 0) {
            int row = warpM * 16 + h * 8 + qrow;
            s_minv[row][warpN] = v;
            s_mini[row][warpN] = idx;
        }
    }
    __syncthreads();
    if (tid < MROWS) {
        float bv = s_minv[tid][0];
        int   bi = s_mini[tid][0];
        float v = s_minv[tid][1];
        int   i = s_mini[tid][1];
        if (v < bv || (v == bv && i < bi)) { bv = v; bi = i; }
        g_idx[rowBase + tid] = bi;
    }
}

// ---------------- kernel 3: gather quantized, loss, scatter EMA stats ----------------
// 4 rows per block, 64 threads/row, float4 per thread.
__global__ void gather_kernel(const float* __restrict__ x, float* __restrict__ out) {
    int tid = threadIdx.x;
    int row = blockIdx.x * 4 + (tid >> 6);
    int c4  = (tid & 63) * 4;
    int idx = g_idx[row];
    const float4 xv = *reinterpret_cast<const float4*>(x + (long)row * DDIM + c4);
    const float4 qv = *reinterpret_cast<const float4*>(g_emb + (long)idx * DDIM + c4);
    *reinterpret_cast<float4*>(out + OFF_Q + (long)row * DDIM + c4) = qv;

    float dx = qv.x - xv.x, dy = qv.y - xv.y, dz = qv.z - xv.z, dw = qv.w - xv.w;
    float s = dx*dx + dy*dy + dz*dz + dw*dw;
    #pragma unroll
    for (int off = 16; off; off >>= 1) s += __shfl_down_sync(0xffffffffu, s, off);
    __shared__ float ws[8];
    if ((tid & 31) == 0) ws[tid >> 5] = s;
    __syncthreads();
    if (tid == 0) {
        float t = 0.f;
        #pragma unroll
        for (int i = 0; i < 8; i++) t += ws[i];
        atomicAdd(&g_loss, t);
    }
    if ((tid & 63) == 0) {
        atomicAdd(&g_counts[idx], 1.0f);
        out[OFF_IDX + row] = (float)idx;
    }
    float* dwp = g_dw + (long)idx * DDIM + c4;
    atomicAdd(dwp + 0, xv.x);
    atomicAdd(dwp + 1, xv.y);
    atomicAdd(dwp + 2, xv.z);
    atomicAdd(dwp + 3, xv.w);
}

// ---------------- kernel 4a: new_cluster_size + sum n ----------------
__global__ void cs_kernel(const float* __restrict__ cluster_size, float* __restrict__ out) {
    int k = blockIdx.x * 256 + threadIdx.x;
    float ncs = cluster_size[k] * DECAY + ONE_M_DECAY * g_counts[k];
    out[OFF_CS + k] = ncs;
    float s = ncs;
    #pragma unroll
    for (int off = 16; off; off >>= 1) s += __shfl_down_sync(0xffffffffu, s, off);
    __shared__ float ws[8];
    if ((threadIdx.x & 31) == 0) ws[threadIdx.x >> 5] = s;
    __syncthreads();
    if (threadIdx.x == 0) {
        float t = 0.f;
        #pragma unroll
        for (int i = 0; i < 8; i++) t += ws[i];
        atomicAdd(&g_nsum, t);
    }
}

// ---------------- kernel 4b: new_ema_w ----------------
__global__ void emaw_kernel(const float* __restrict__ ema_w, float* __restrict__ out) {
    long i = (long)blockIdx.x * blockDim.x + threadIdx.x;
    if (i < (long)KCODES * DDIM)
        out[OFF_EMAW + i] = ema_w[i] * DECAY + ONE_M_DECAY * g_dw[i];
}

// ---------------- kernel 5: smoothed normalize + loss write ----------------
__global__ void final_kernel(float* __restrict__ out) {
    int k = blockIdx.x;
    int d = threadIdx.x;
    float n = g_nsum;
    float ncs = out[OFF_CS + k];
    float smoothed = (ncs + EPSV) / (n + (float)KCODES * EPSV) * n;
    out[OFF_EMB + (long)k * DDIM + d] = out[OFF_EMAW + (long)k * DDIM + d] / smoothed;
    if (k == 0 && d == 0)
        out[OFF_LOSS] = 2.0f * g_loss / (float)((long)NROWS * DDIM);
}

// ---------------- launch ----------------
extern "C" void kernel_launch(void* const* d_in, const int* in_sizes, int n_in,
                              void* d_out, int out_size) {
    const float* x         = (const float*)d_in[0];
    const float* embedding = (const float*)d_in[1];
    const float* amean     = (const float*)d_in[2];
    const float* astd      = (const float*)d_in[3];
    const float* cs        = (const float*)d_in[4];
    const float* ema_w     = (const float*)d_in[5];
    float* out = (float*)d_out;

    (void)in_sizes; (void)n_in; (void)out_size;

    cudaFuncSetAttribute(argmin_kernel, cudaFuncAttributeMaxDynamicSharedMemorySize,
                         2 * BUF_U * 2);

    zero_kernel<<<2048, 256>>>();
    xsplit_kernel<<<NROWS * DDIM / 256, 256>>>(x);
    prep_kernel<<<KCODES, 256>>>(embedding, amean, astd);
    argmin_kernel<<<NROWS_PAD / MROWS, NTHREADS, 2 * BUF_U * 2>>>();
    gather_kernel<<<NROWS / 4, 256>>>(x, out);
    cs_kernel<<<KCODES / 256, 256>>>(cs, out);
    emaw_kernel<<<(KCODES * DDIM + 255) / 256, 256>>>(ema_w, out);
    final_kernel<<<KCODES, 256>>>(out);
}